// round 16
// baseline (speedup 1.0000x reference)
#include <cuda_runtime.h>
#include <cuda_fp16.h>
#include <cstdint>
#include <math.h>

// ---------------------------------------------------------------------------
// PairwiseInteractionHead B=4, L=256, D=256, H=128, TOPK=100.
// Round 15: exact R12 structure (best, 268.8us) + warp-aggregated
// (__match_any_sync) histogram atomics in topk. No other changes.
// ---------------------------------------------------------------------------

#define NB 4
#define NPAIR_B 65536
#define TOPK_K 100
#define XSCALE 32.0f
#define XINV   0.03125f

__device__ float g_lproj[NB * 256 * 256];
__device__ float g_pproj[NB * 256 * 256];
__device__ float g_A1[NB * 256 * 128];
__device__ float g_B1[NB * 256 * 128];
__device__ int   g_lmask[NB * 256];
__device__ int   g_pmask[NB * 256];
__device__ __half g_W1h[128 * 512];
__device__ __half g_W2h[128 * 128];

// fast gelu: Abramowitz-Stegun 7.1.26 erf approx (|err| <= 1.5e-7 abs)
__device__ __forceinline__ float gelu_f(float x) {
    float y = fabsf(x) * 0.70710678118654752440f;
    float t = __fdividef(1.0f, fmaf(0.3275911f, y, 1.0f));
    float poly = t * fmaf(t, fmaf(t, fmaf(t, fmaf(t, 1.061405429f, -1.453152027f),
                        1.421413741f), -0.284496736f), 0.254829592f);
    float e = __expf(-y * y);
    float erfy = fmaf(-poly, e, 1.0f);
    float erfx = copysignf(erfy, x);
    return 0.5f * x * (1.0f + erfx);
}

// -------------------- low-level helpers --------------------
__device__ __forceinline__ uint32_t smem_u32(const void* p) {
    uint32_t a;
    asm("{ .reg .u64 t; cvta.to.shared.u64 t, %1; cvt.u32.u64 %0, t; }" : "=r"(a) : "l"(p));
    return a;
}
__device__ __forceinline__ uint32_t packh(float x0, float x1) {
    uint32_t d;
    asm("cvt.rn.f16x2.f32 %0, %1, %2;" : "=r"(d) : "f"(x1), "f"(x0));
    return d;
}
__device__ __forceinline__ uint32_t hmul2u(uint32_t a, uint32_t b) {
    __half2 r = __hmul2(*(__half2*)&a, *(__half2*)&b);
    return *(uint32_t*)&r;
}
__device__ __forceinline__ uint32_t habsdiff2u(uint32_t a, uint32_t b) {
    __half2 r = __habs2(__hsub2(*(__half2*)&a, *(__half2*)&b));
    return *(uint32_t*)&r;
}
__device__ __forceinline__ void ldsm_x4(uint32_t* r, uint32_t addr) {
    asm volatile("ldmatrix.sync.aligned.m8n8.x4.shared.b16 {%0,%1,%2,%3}, [%4];"
        : "=r"(r[0]), "=r"(r[1]), "=r"(r[2]), "=r"(r[3]) : "r"(addr));
}
__device__ __forceinline__ void mma_f16(float* c, const uint32_t* a, uint32_t b0, uint32_t b1) {
    asm volatile(
        "mma.sync.aligned.m16n8k16.row.col.f32.f16.f16.f32 "
        "{%0,%1,%2,%3}, {%4,%5,%6,%7}, {%8,%9}, {%0,%1,%2,%3};"
        : "+f"(c[0]), "+f"(c[1]), "+f"(c[2]), "+f"(c[3])
        : "r"(a[0]), "r"(a[1]), "r"(a[2]), "r"(a[3]), "r"(b0), "r"(b1));
}

// -------------------- fused prep: detect+mask (blocks 0-1) + wprep ----------
__global__ __launch_bounds__(1024) void prep_kernel(
    const void* lpad, const void* ppad,
    const float* __restrict__ W1, const float* __restrict__ W2)
{
    const int blk = blockIdx.x;
    if (blk < 2) {
        const unsigned char* p = (const unsigned char*)(blk ? ppad : lpad);
        __shared__ int s_nonbin, s_oddnz, s_anynz, s_flag;
        if (threadIdx.x == 0) { s_nonbin = 0; s_oddnz = 0; s_anynz = 0; }
        __syncthreads();
        if (threadIdx.x < 256) {
            int nonbin = 0, oddnz = 0, anynz = 0;
            for (int i = threadIdx.x; i < 1024; i += 256) {
                unsigned v = p[i];
                if (v) { anynz = 1; if (v > 1u) nonbin = 1; if (i & 3) oddnz = 1; }
            }
            if (nonbin) atomicOr(&s_nonbin, 1);
            if (oddnz)  atomicOr(&s_oddnz, 1);
            if (anynz)  atomicOr(&s_anynz, 1);
        }
        __syncthreads();
        if (threadIdx.x == 0) {
            int f;
            if (!s_anynz) f = 0;
            else if (s_nonbin) f = 2;
            else if (s_oddnz) f = 1;
            else f = 3;
            s_flag = f;
        }
        __syncthreads();
        const int f = s_flag;
        const int i = threadIdx.x;
        int m;
        if (f == 0) m = 0;
        else if (f == 1) m = (((const unsigned char*)p)[i] != 0);
        else if (f == 2) m = (((const float*)p)[i] != 0.0f);
        else m = (((const int*)p)[i] != 0);
        (blk ? g_pmask : g_lmask)[i] = m;
    } else {
        int i = (blk - 2) * 1024 + threadIdx.x;
        if (i < 128 * 512) {
            g_W1h[i] = __float2half_rn(W1[(i >> 9) * 1024 + 512 + (i & 511)]);
        } else {
            int j = i - 128 * 512;
            if (j < 128 * 128) g_W2h[j] = __float2half_rn(W2[j]);
        }
    }
}

// -------------------- projection GEMM (R1, proven) --------------------
__global__ __launch_bounds__(256) void proj_kernel(
    const float* __restrict__ ltok, const float* __restrict__ ptok,
    const float* __restrict__ Wl, const float* __restrict__ bl,
    const float* __restrict__ Wp, const float* __restrict__ bp)
{
    __shared__ float As[16][68];
    __shared__ float Bs[16][68];
    const int n0 = blockIdx.x * 64;
    const int m0 = blockIdx.y * 64;
    const bool isP = (m0 >= 1024);
    const float* in   = isP ? ptok : ltok;
    const float* W    = isP ? Wp : Wl;
    const float* bias = isP ? bp : bl;
    const int mb = isP ? (m0 - 1024) : m0;
    float* outp = isP ? g_pproj : g_lproj;
    const int tid = threadIdx.x;
    const int tx = tid & 15, ty = tid >> 4;
    const int lr = tid >> 2, lc = (tid & 3) * 4;
    float acc[4][4] = {};
    for (int kt = 0; kt < 256; kt += 16) {
        float4 a4 = *(const float4*)&in[(mb + lr) * 256 + kt + lc];
        float4 b4 = *(const float4*)&W[(n0 + lr) * 256 + kt + lc];
        As[lc + 0][lr] = a4.x; As[lc + 1][lr] = a4.y; As[lc + 2][lr] = a4.z; As[lc + 3][lr] = a4.w;
        Bs[lc + 0][lr] = b4.x; Bs[lc + 1][lr] = b4.y; Bs[lc + 2][lr] = b4.z; Bs[lc + 3][lr] = b4.w;
        __syncthreads();
#pragma unroll
        for (int e = 0; e < 16; e++) {
            float4 av = *(const float4*)&As[e][ty * 4];
            float4 bv = *(const float4*)&Bs[e][tx * 4];
            acc[0][0] += av.x * bv.x; acc[0][1] += av.x * bv.y; acc[0][2] += av.x * bv.z; acc[0][3] += av.x * bv.w;
            acc[1][0] += av.y * bv.x; acc[1][1] += av.y * bv.y; acc[1][2] += av.y * bv.z; acc[1][3] += av.y * bv.w;
            acc[2][0] += av.z * bv.x; acc[2][1] += av.z * bv.y; acc[2][2] += av.z * bv.z; acc[2][3] += av.z * bv.w;
            acc[3][0] += av.w * bv.x; acc[3][1] += av.w * bv.y; acc[3][2] += av.w * bv.z; acc[3][3] += av.w * bv.w;
        }
        __syncthreads();
    }
#pragma unroll
    for (int ii = 0; ii < 4; ii++)
#pragma unroll
        for (int jj = 0; jj < 4; jj++) {
            int n = n0 + tx * 4 + jj;
            outp[(mb + ty * 4 + ii) * 256 + n] = acc[ii][jj] + bias[n];
        }
}

// -------------------- A1/B1 GEMM (R1, proven) --------------------
__global__ __launch_bounds__(256) void a1b1_kernel(
    const float* __restrict__ W1, const float* __restrict__ b1)
{
    __shared__ float As[16][68];
    __shared__ float Bs[16][68];
    const int n0 = blockIdx.x * 64;
    const int m0 = blockIdx.y * 64;
    const bool isP = (m0 >= 1024);
    const float* in = isP ? g_pproj : g_lproj;
    const int mb = isP ? (m0 - 1024) : m0;
    const int colOff = isP ? 256 : 0;
    float* outp = isP ? g_B1 : g_A1;
    const int tid = threadIdx.x;
    const int tx = tid & 15, ty = tid >> 4;
    const int lr = tid >> 2, lc = (tid & 3) * 4;
    float acc[4][4] = {};
    for (int kt = 0; kt < 256; kt += 16) {
        float4 a4 = *(const float4*)&in[(mb + lr) * 256 + kt + lc];
        float4 b4 = *(const float4*)&W1[(n0 + lr) * 1024 + colOff + kt + lc];
        As[lc + 0][lr] = a4.x; As[lc + 1][lr] = a4.y; As[lc + 2][lr] = a4.z; As[lc + 3][lr] = a4.w;
        Bs[lc + 0][lr] = b4.x; Bs[lc + 1][lr] = b4.y; Bs[lc + 2][lr] = b4.z; Bs[lc + 3][lr] = b4.w;
        __syncthreads();
#pragma unroll
        for (int e = 0; e < 16; e++) {
            float4 av = *(const float4*)&As[e][ty * 4];
            float4 bv = *(const float4*)&Bs[e][tx * 4];
            acc[0][0] += av.x * bv.x; acc[0][1] += av.x * bv.y; acc[0][2] += av.x * bv.z; acc[0][3] += av.x * bv.w;
            acc[1][0] += av.y * bv.x; acc[1][1] += av.y * bv.y; acc[1][2] += av.y * bv.z; acc[1][3] += av.y * bv.w;
            acc[2][0] += av.z * bv.x; acc[2][1] += av.z * bv.y; acc[2][2] += av.z * bv.z; acc[2][3] += av.z * bv.w;
            acc[3][0] += av.w * bv.x; acc[3][1] += av.w * bv.y; acc[3][2] += av.w * bv.z; acc[3][3] += av.w * bv.w;
        }
        __syncthreads();
    }
#pragma unroll
    for (int ii = 0; ii < 4; ii++)
#pragma unroll
        for (int jj = 0; jj < 4; jj++) {
            int n = n0 + tx * 4 + jj;
            float bv = isP ? 0.0f : b1[n];
            outp[(mb + ty * 4 + ii) * 128 + n] = acc[ii][jj] + bv;
        }
}

// -------------------- tensor-core pair kernel (R12) --------------------
#define SM_LH32  0u
#define SM_PH    8448u
#define SM_PH32  16896u
#define SM_X0    25344u
#define SM_X1    62208u
#define SM_W0    99072u
#define SM_W1B   117504u
#define SM_A1    135936u
#define SM_B1    144384u
#define SM_YH(c)  ((c) * 20480u)
#define SM_W2H    81920u           // [128][272B]
#define SM_ZP     116736u          // [4][256] f32
#define SMEM_PAIR 152832

__global__ __launch_bounds__(512, 1) void pair_kernel(
    const float* __restrict__ b2g, const float* __restrict__ W3,
    const float* __restrict__ b3, float* __restrict__ out)
{
    extern __shared__ char smc[];
    float* A1s = (float*)(smc + SM_A1);
    float* B1s = (float*)(smc + SM_B1);
    const uint32_t sbase = smem_u32(smc);

    const int tid  = threadIdx.x;
    const int lane = tid & 31;
    const int wid  = tid >> 5;
    const int mw   = wid & 3;
    const int nw   = wid >> 2;
    const int b  = blockIdx.z;
    const int it = blockIdx.y * 16;
    const int jt = blockIdx.x * 16;

    const uint32_t xOff[2] = {SM_X0, SM_X1};
    const uint32_t wOff[2] = {SM_W0, SM_W1B};

    const uint32_t a_row  = (lane & 7) + ((lane >> 3) & 1) * 8;
    const uint32_t a_colh = ((lane >> 4) & 1) * 16;
    const uint32_t b_row16 = (lane & 7) + ((lane >> 4) & 1) * 8;
    const uint32_t b_colh  = ((lane >> 3) & 1) * 16;

    {
        const float* lsrc = g_lproj + (size_t)(b * 256 + it) * 256;
        const float* psrc = g_pproj + (size_t)(b * 256 + jt) * 256;
        int r = tid >> 5;
        int c = (tid & 31) * 8;
        const float* lr_ = lsrc + r * 256 + c;
        const float* pr_ = psrc + r * 256 + c;
        float4 l0 = *(const float4*)lr_;
        float4 l1 = *(const float4*)(lr_ + 4);
        float4 p0 = *(const float4*)pr_;
        float4 p1 = *(const float4*)(pr_ + 4);
        uint4 lh;
        lh.x = packh(XSCALE * l0.x, XSCALE * l0.y);
        lh.y = packh(XSCALE * l0.z, XSCALE * l0.w);
        lh.z = packh(XSCALE * l1.x, XSCALE * l1.y);
        lh.w = packh(XSCALE * l1.z, XSCALE * l1.w);
        *(uint4*)(smc + SM_LH32 + r * 528 + c * 2) = lh;
        uint4 ph;
        ph.x = packh(p0.x, p0.y);
        ph.y = packh(p0.z, p0.w);
        ph.z = packh(p1.x, p1.y);
        ph.w = packh(p1.z, p1.w);
        *(uint4*)(smc + SM_PH + r * 528 + c * 2) = ph;
        uint4 ph32;
        ph32.x = packh(XSCALE * p0.x, XSCALE * p0.y);
        ph32.y = packh(XSCALE * p0.z, XSCALE * p0.w);
        ph32.z = packh(XSCALE * p1.x, XSCALE * p1.y);
        ph32.w = packh(XSCALE * p1.z, XSCALE * p1.w);
        *(uint4*)(smc + SM_PH32 + r * 528 + c * 2) = ph32;

        const float* a1src = g_A1 + (size_t)(b * 256 + it) * 128;
        const float* b1src = g_B1 + (size_t)(b * 256 + jt) * 128;
        int rc = (tid & 31) * 4;
        *(float4*)&A1s[r * 132 + rc] = *(const float4*)&a1src[r * 128 + rc];
        *(float4*)&B1s[r * 132 + rc] = *(const float4*)&b1src[r * 128 + rc];
    }

    float acc[4][4][4];
#pragma unroll
    for (int mt = 0; mt < 4; mt++)
#pragma unroll
        for (int nt = 0; nt < 4; nt++)
#pragma unroll
            for (int r = 0; r < 4; r++) acc[mt][nt][r] = 0.0f;

    const int bp_ = tid & 255;
    const int bkh = tid >> 8;
    const char* lbase   = smc + SM_LH32 + (bp_ >> 4) * 528;
    const char* pbase   = smc + SM_PH   + (bp_ & 15) * 528;
    const char* p32base = smc + SM_PH32 + (bp_ & 15) * 528;

    __syncthreads();

#define BUILD_CHUNK(cn, sn) do { \
        const bool mul_ = ((cn) < 4); \
        const int kb_ = ((cn) & 3) * 64 + bkh * 32; \
        const uint4* ls_ = (const uint4*)(lbase + kb_ * 2); \
        const uint4* ps_ = (const uint4*)((mul_ ? pbase : p32base) + kb_ * 2); \
        char* dst_ = smc + xOff[sn] + bp_ * 144 + bkh * 64; \
        _Pragma("unroll") \
        for (int q_ = 0; q_ < 4; q_++) { \
            uint4 lv_ = ls_[q_]; \
            uint4 pv_ = ps_[q_]; \
            uint4 ov_; \
            if (mul_) { \
                ov_.x = hmul2u(lv_.x, pv_.x); ov_.y = hmul2u(lv_.y, pv_.y); \
                ov_.z = hmul2u(lv_.z, pv_.z); ov_.w = hmul2u(lv_.w, pv_.w); \
            } else { \
                ov_.x = habsdiff2u(lv_.x, pv_.x); ov_.y = habsdiff2u(lv_.y, pv_.y); \
                ov_.z = habsdiff2u(lv_.z, pv_.z); ov_.w = habsdiff2u(lv_.w, pv_.w); \
            } \
            *(uint4*)(dst_ + q_ * 16) = ov_; \
        } \
        const int wr_ = tid >> 2; \
        const int ws_ = tid & 3; \
        const uint4* wsrc_ = (const uint4*)(g_W1h + wr_ * 512 + (cn) * 64 + ws_ * 16); \
        char* wdst_ = smc + wOff[sn] + wr_ * 144 + ws_ * 32; \
        *(uint4*)(wdst_)      = wsrc_[0]; \
        *(uint4*)(wdst_ + 16) = wsrc_[1]; \
    } while (0)

    BUILD_CHUNK(0, 0);
    __syncthreads();

    for (int c = 0; c < 8; c++) {
        const int s = c & 1;
        if (c + 1 < 8) BUILD_CHUNK(c + 1, (c + 1) & 1);
#pragma unroll
        for (int ks = 0; ks < 4; ks++) {
            uint32_t ah[4][4];
            uint32_t bh[2][4];
#pragma unroll
            for (int mt = 0; mt < 4; mt++) {
                uint32_t rowa = (uint32_t)(mw * 64 + mt * 16) + a_row;
                ldsm_x4(ah[mt], sbase + xOff[s] + rowa * 144 + ks * 32 + a_colh);
            }
#pragma unroll
            for (int ntp = 0; ntp < 2; ntp++) {
                uint32_t rowb = (uint32_t)(nw * 32 + ntp * 16) + b_row16;
                ldsm_x4(bh[ntp], sbase + wOff[s] + rowb * 144 + ks * 32 + b_colh);
            }
#pragma unroll
            for (int ntp = 0; ntp < 2; ntp++)
#pragma unroll
                for (int half = 0; half < 2; half++)
#pragma unroll
                    for (int mt = 0; mt < 4; mt++)
                        mma_f16(acc[mt][ntp * 2 + half], ah[mt],
                                bh[ntp][half * 2], bh[ntp][half * 2 + 1]);
        }
        __syncthreads();
    }
#undef BUILD_CHUNK

#pragma unroll
    for (int mt = 0; mt < 4; mt++) {
#pragma unroll
        for (int rh = 0; rh < 2; rh++) {
            int row = mw * 64 + mt * 16 + (lane >> 2) + rh * 8;
            int il = row >> 4, jl = row & 15;
#pragma unroll
            for (int nt = 0; nt < 4; nt++) {
                int colb = nw * 32 + nt * 8 + (lane & 3) * 2;
                float2 a1v = *(const float2*)&A1s[il * 132 + colb];
                float2 b1v = *(const float2*)&B1s[jl * 132 + colb];
                acc[mt][nt][rh * 2 + 0] = gelu_f(acc[mt][nt][rh * 2 + 0] * XINV + a1v.x + b1v.x);
                acc[mt][nt][rh * 2 + 1] = gelu_f(acc[mt][nt][rh * 2 + 1] * XINV + a1v.y + b1v.y);
            }
        }
    }
    __syncthreads();

#pragma unroll
    for (int mt = 0; mt < 4; mt++) {
#pragma unroll
        for (int nt = 0; nt < 4; nt++) {
#pragma unroll
            for (int rh = 0; rh < 2; rh++) {
                int row = mw * 64 + mt * 16 + (lane >> 2) + rh * 8;
                int cloc = nt * 8 + (lane & 3) * 2;
                uint32_t hp = packh(XSCALE * acc[mt][nt][rh * 2 + 0],
                                    XSCALE * acc[mt][nt][rh * 2 + 1]);
                *(uint32_t*)(smc + SM_YH(nw) + row * 80 + cloc * 2) = hp;
            }
        }
    }
    {
        const int wr = tid >> 2;
        const int ws = tid & 3;
        const uint4* wsrc = (const uint4*)(g_W2h + wr * 128 + ws * 32);
        char* wdst = smc + SM_W2H + wr * 272 + ws * 64;
        *(uint4*)(wdst)      = wsrc[0];
        *(uint4*)(wdst + 16) = wsrc[1];
        *(uint4*)(wdst + 32) = wsrc[2];
        *(uint4*)(wdst + 48) = wsrc[3];
    }
#pragma unroll
    for (int mt = 0; mt < 4; mt++)
#pragma unroll
        for (int nt = 0; nt < 4; nt++)
#pragma unroll
            for (int r = 0; r < 4; r++) acc[mt][nt][r] = 0.0f;
    __syncthreads();

#pragma unroll
    for (int ks = 0; ks < 8; ks++) {
        uint32_t ah[4][4];
        uint32_t bh[2][4];
#pragma unroll
        for (int mt = 0; mt < 4; mt++) {
            uint32_t rowa = (uint32_t)(mw * 64 + mt * 16) + a_row;
            ldsm_x4(ah[mt], sbase + SM_YH(ks >> 1) + rowa * 80 + (ks & 1) * 32 + a_colh);
        }
#pragma unroll
        for (int ntp = 0; ntp < 2; ntp++) {
            uint32_t rowb = (uint32_t)(nw * 32 + ntp * 16) + b_row16;
            ldsm_x4(bh[ntp], sbase + SM_W2H + rowb * 272 + ks * 32 + b_colh);
        }
#pragma unroll
        for (int ntp = 0; ntp < 2; ntp++)
#pragma unroll
            for (int half = 0; half < 2; half++)
#pragma unroll
                for (int mt = 0; mt < 4; mt++)
                    mma_f16(acc[mt][ntp * 2 + half], ah[mt],
                            bh[ntp][half * 2], bh[ntp][half * 2 + 1]);
    }
    __syncthreads();

    {
        float part[4][2];
#pragma unroll
        for (int mt = 0; mt < 4; mt++) { part[mt][0] = 0.0f; part[mt][1] = 0.0f; }
#pragma unroll
        for (int nt = 0; nt < 4; nt++) {
            int colb = nw * 32 + nt * 8 + (lane & 3) * 2;
            float w3a = __ldg(W3 + colb), w3b = __ldg(W3 + colb + 1);
            float b2a = __ldg(b2g + colb), b2b = __ldg(b2g + colb + 1);
#pragma unroll
            for (int mt = 0; mt < 4; mt++) {
                part[mt][0] += w3a * gelu_f(acc[mt][nt][0] * XINV + b2a) + w3b * gelu_f(acc[mt][nt][1] * XINV + b2b);
                part[mt][1] += w3a * gelu_f(acc[mt][nt][2] * XINV + b2a) + w3b * gelu_f(acc[mt][nt][3] * XINV + b2b);
            }
        }
#pragma unroll
        for (int off = 1; off <= 2; off <<= 1) {
#pragma unroll
            for (int mt = 0; mt < 4; mt++) {
                part[mt][0] += __shfl_xor_sync(0xFFFFFFFFu, part[mt][0], off);
                part[mt][1] += __shfl_xor_sync(0xFFFFFFFFu, part[mt][1], off);
            }
        }
        if ((lane & 3) == 0) {
            float* ZP = (float*)(smc + SM_ZP);
#pragma unroll
            for (int mt = 0; mt < 4; mt++) {
                int row0 = mw * 64 + mt * 16 + (lane >> 2);
                ZP[nw * 256 + row0]     = part[mt][0];
                ZP[nw * 256 + row0 + 8] = part[mt][1];
            }
        }
    }
    __syncthreads();
    if (tid < 256) {
        const float* ZP = (const float*)(smc + SM_ZP);
        float v = ZP[tid] + ZP[256 + tid] + ZP[512 + tid] + ZP[768 + tid] + b3[0];
        if (isnan(v)) v = 0.0f;
        else if (isinf(v)) v = (v > 0.0f) ? 20.0f : -20.0f;
        const int gi = it + (tid >> 4);
        const int gj = jt + (tid & 15);
        if (g_lmask[b * 256 + gi] || g_pmask[b * 256 + gj]) v = -20.0f;
        const int idx = 4 + (b * 65536 + gi * 256 + gj);
        out[idx] = v;
        out[idx + 262144] = 1.0f / (1.0f + expf(-v));
    }
}

// -------------------- top-k: aggregated-atomic byte-radix --------------------
__device__ __forceinline__ int wredsum_i(int v) {
#pragma unroll
    for (int o = 16; o; o >>= 1) v += __shfl_xor_sync(0xFFFFFFFFu, v, o);
    return v;
}
__device__ __forceinline__ float wredsum_f(float v) {
#pragma unroll
    for (int o = 16; o; o >>= 1) v += __shfl_xor_sync(0xFFFFFFFFu, v, o);
    return v;
}
__device__ __forceinline__ unsigned fkey(float v) {
    unsigned u = __float_as_uint(v);
    return (u & 0x80000000u) ? ~u : (u | 0x80000000u);
}
// warp-aggregated histogram add: lanes with the same bin elect one leader
// which adds popc(match) once. Inactive lanes use a unique sentinel key.
__device__ __forceinline__ void hist_add(int* hist, unsigned k, unsigned prefix,
                                         unsigned maskHi, int bpos, int lane) {
    const bool act = ((k ^ prefix) & maskHi) == 0;
    const unsigned bin = (k >> bpos) & 255u;
    const unsigned key = act ? bin : (0x100u + (unsigned)lane);
    const unsigned mm = __match_any_sync(0xFFFFFFFFu, key);
    if (act && lane == (__ffs(mm) - 1))
        atomicAdd(&hist[bin], __popc(mm));
}

__global__ __launch_bounds__(1024) void topk_kernel(float* out) {
    const int b = blockIdx.x;
    const float* data = out + 4 + b * NPAIR_B;
    const int tid = threadIdx.x, lane = tid & 31, wid = tid >> 5;
    __shared__ int histW[32][257];
    __shared__ unsigned s_pref;
    __shared__ int s_above;
    __shared__ float sf[32], sf2[32];
    __shared__ int si[32];

    unsigned prefix = 0u;
    int above = 0;
    for (int pass = 0; pass < 4; pass++) {
        const int bpos = 24 - 8 * pass;
        for (int i = tid; i < 32 * 257; i += 1024) (&histW[0][0])[i] = 0;
        __syncthreads();
        const unsigned maskHi = (pass == 0) ? 0u : (0xFFFFFFFFu << (bpos + 8));
        int* myhist = histW[wid];
#pragma unroll 4
        for (int i = tid * 4; i < NPAIR_B; i += 4096) {
            float4 v4 = *(const float4*)(data + i);
            hist_add(myhist, fkey(v4.x), prefix, maskHi, bpos, lane);
            hist_add(myhist, fkey(v4.y), prefix, maskHi, bpos, lane);
            hist_add(myhist, fkey(v4.z), prefix, maskHi, bpos, lane);
            hist_add(myhist, fkey(v4.w), prefix, maskHi, bpos, lane);
        }
        __syncthreads();
        if (tid < 256) {
            int s = 0;
#pragma unroll
            for (int w = 0; w < 32; w++) s += histW[w][tid];
            histW[0][tid] = s;
        }
        __syncthreads();
        if (tid == 0) {
            int run = 0, chosen = 0, abv = above;
            for (int x = 255; x >= 0; --x) {
                int nr = run + histW[0][x];
                if (above + nr >= TOPK_K) { chosen = x; abv = above + run; break; }
                run = nr;
            }
            s_pref = prefix | ((unsigned)chosen << bpos);
            s_above = abv;
        }
        __syncthreads();
        prefix = s_pref;
        above = s_above;
        __syncthreads();
    }

    unsigned ut = (prefix & 0x80000000u) ? (prefix & 0x7FFFFFFFu) : ~prefix;
    const float vT = __uint_as_float(ut);

    float s1 = 0.0f, s2 = 0.0f;
    int cg = 0;
#pragma unroll 4
    for (int i = tid * 4; i < NPAIR_B; i += 4096) {
        float4 v4 = *(const float4*)(data + i);
        float vv[4] = {v4.x, v4.y, v4.z, v4.w};
#pragma unroll
        for (int q = 0; q < 4; q++) {
            if (fkey(vv[q]) > prefix) {
                float e = __expf(vv[q] - vT);
                s1 += e; s2 += e * vv[q]; cg++;
            }
        }
    }
    s1 = wredsum_f(s1);
    s2 = wredsum_f(s2);
    cg = wredsum_i(cg);
    if (lane == 0) { sf[wid] = s1; sf2[wid] = s2; si[wid] = cg; }
    __syncthreads();
    if (tid == 0) {
        float S1 = 0.0f, S2 = 0.0f;
        int CG = 0;
        for (int w = 0; w < 32; w++) { S1 += sf[w]; S2 += sf2[w]; CG += si[w]; }
        int r = TOPK_K - CG;
        S1 += (float)r;
        S2 += (float)r * vT;
        out[b] = S2 / S1;
    }
}

// ---------------------------------------------------------------------------
extern "C" void kernel_launch(void* const* d_in, const int* in_sizes, int n_in,
                              void* d_out, int out_size)
{
    const float* ltok = (const float*)d_in[0];
    const float* ptok = (const float*)d_in[1];
    const void*  lpad = d_in[2];
    const void*  ppad = d_in[3];
    const float* Wl = (const float*)d_in[4];
    const float* bl = (const float*)d_in[5];
    const float* Wp = (const float*)d_in[6];
    const float* bp = (const float*)d_in[7];
    const float* W1 = (const float*)d_in[8];
    const float* b1 = (const float*)d_in[9];
    const float* W2 = (const float*)d_in[10];
    const float* b2 = (const float*)d_in[11];
    const float* W3 = (const float*)d_in[12];
    const float* b3 = (const float*)d_in[13];
    float* out = (float*)d_out;

    prep_kernel<<<82, 1024>>>(lpad, ppad, W1, W2);
    proj_kernel<<<dim3(4, 32), 256>>>(ltok, ptok, Wl, bl, Wp, bp);
    a1b1_kernel<<<dim3(2, 32), 256>>>(W1, b1);

    cudaFuncSetAttribute(pair_kernel, cudaFuncAttributeMaxDynamicSharedMemorySize, SMEM_PAIR);
    pair_kernel<<<dim3(16, 16, 4), 512, SMEM_PAIR>>>(b2, W3, b3, out);

    topk_kernel<<<4, 1024>>>(out);
}

// round 17
// speedup vs baseline: 1.7051x; 1.7051x over previous
#include <cuda_runtime.h>
#include <cuda_fp16.h>
#include <cstdint>
#include <math.h>

// ---------------------------------------------------------------------------
// PairwiseInteractionHead B=4, L=256, D=256, H=128, TOPK=100.
// Round 16: exact R12 (best, 268.8us) + 8-elem/thread ILP in topk scans.
// ---------------------------------------------------------------------------

#define NB 4
#define NPAIR_B 65536
#define TOPK_K 100
#define XSCALE 32.0f
#define XINV   0.03125f

__device__ float g_lproj[NB * 256 * 256];
__device__ float g_pproj[NB * 256 * 256];
__device__ float g_A1[NB * 256 * 128];
__device__ float g_B1[NB * 256 * 128];
__device__ int   g_lmask[NB * 256];
__device__ int   g_pmask[NB * 256];
__device__ __half g_W1h[128 * 512];
__device__ __half g_W2h[128 * 128];

// fast gelu: Abramowitz-Stegun 7.1.26 erf approx (|err| <= 1.5e-7 abs)
__device__ __forceinline__ float gelu_f(float x) {
    float y = fabsf(x) * 0.70710678118654752440f;
    float t = __fdividef(1.0f, fmaf(0.3275911f, y, 1.0f));
    float poly = t * fmaf(t, fmaf(t, fmaf(t, fmaf(t, 1.061405429f, -1.453152027f),
                        1.421413741f), -0.284496736f), 0.254829592f);
    float e = __expf(-y * y);
    float erfy = fmaf(-poly, e, 1.0f);
    float erfx = copysignf(erfy, x);
    return 0.5f * x * (1.0f + erfx);
}

// -------------------- low-level helpers --------------------
__device__ __forceinline__ uint32_t smem_u32(const void* p) {
    uint32_t a;
    asm("{ .reg .u64 t; cvta.to.shared.u64 t, %1; cvt.u32.u64 %0, t; }" : "=r"(a) : "l"(p));
    return a;
}
__device__ __forceinline__ uint32_t packh(float x0, float x1) {
    uint32_t d;
    asm("cvt.rn.f16x2.f32 %0, %1, %2;" : "=r"(d) : "f"(x1), "f"(x0));
    return d;
}
__device__ __forceinline__ uint32_t hmul2u(uint32_t a, uint32_t b) {
    __half2 r = __hmul2(*(__half2*)&a, *(__half2*)&b);
    return *(uint32_t*)&r;
}
__device__ __forceinline__ uint32_t habsdiff2u(uint32_t a, uint32_t b) {
    __half2 r = __habs2(__hsub2(*(__half2*)&a, *(__half2*)&b));
    return *(uint32_t*)&r;
}
__device__ __forceinline__ void ldsm_x4(uint32_t* r, uint32_t addr) {
    asm volatile("ldmatrix.sync.aligned.m8n8.x4.shared.b16 {%0,%1,%2,%3}, [%4];"
        : "=r"(r[0]), "=r"(r[1]), "=r"(r[2]), "=r"(r[3]) : "r"(addr));
}
__device__ __forceinline__ void mma_f16(float* c, const uint32_t* a, uint32_t b0, uint32_t b1) {
    asm volatile(
        "mma.sync.aligned.m16n8k16.row.col.f32.f16.f16.f32 "
        "{%0,%1,%2,%3}, {%4,%5,%6,%7}, {%8,%9}, {%0,%1,%2,%3};"
        : "+f"(c[0]), "+f"(c[1]), "+f"(c[2]), "+f"(c[3])
        : "r"(a[0]), "r"(a[1]), "r"(a[2]), "r"(a[3]), "r"(b0), "r"(b1));
}

// -------------------- fused prep: detect+mask (blocks 0-1) + wprep ----------
__global__ __launch_bounds__(1024) void prep_kernel(
    const void* lpad, const void* ppad,
    const float* __restrict__ W1, const float* __restrict__ W2)
{
    const int blk = blockIdx.x;
    if (blk < 2) {
        const unsigned char* p = (const unsigned char*)(blk ? ppad : lpad);
        __shared__ int s_nonbin, s_oddnz, s_anynz, s_flag;
        if (threadIdx.x == 0) { s_nonbin = 0; s_oddnz = 0; s_anynz = 0; }
        __syncthreads();
        if (threadIdx.x < 256) {
            int nonbin = 0, oddnz = 0, anynz = 0;
            for (int i = threadIdx.x; i < 1024; i += 256) {
                unsigned v = p[i];
                if (v) { anynz = 1; if (v > 1u) nonbin = 1; if (i & 3) oddnz = 1; }
            }
            if (nonbin) atomicOr(&s_nonbin, 1);
            if (oddnz)  atomicOr(&s_oddnz, 1);
            if (anynz)  atomicOr(&s_anynz, 1);
        }
        __syncthreads();
        if (threadIdx.x == 0) {
            int f;
            if (!s_anynz) f = 0;
            else if (s_nonbin) f = 2;
            else if (s_oddnz) f = 1;
            else f = 3;
            s_flag = f;
        }
        __syncthreads();
        const int f = s_flag;
        const int i = threadIdx.x;
        int m;
        if (f == 0) m = 0;
        else if (f == 1) m = (((const unsigned char*)p)[i] != 0);
        else if (f == 2) m = (((const float*)p)[i] != 0.0f);
        else m = (((const int*)p)[i] != 0);
        (blk ? g_pmask : g_lmask)[i] = m;
    } else {
        int i = (blk - 2) * 1024 + threadIdx.x;
        if (i < 128 * 512) {
            g_W1h[i] = __float2half_rn(W1[(i >> 9) * 1024 + 512 + (i & 511)]);
        } else {
            int j = i - 128 * 512;
            if (j < 128 * 128) g_W2h[j] = __float2half_rn(W2[j]);
        }
    }
}

// -------------------- projection GEMM (R1, proven) --------------------
__global__ __launch_bounds__(256) void proj_kernel(
    const float* __restrict__ ltok, const float* __restrict__ ptok,
    const float* __restrict__ Wl, const float* __restrict__ bl,
    const float* __restrict__ Wp, const float* __restrict__ bp)
{
    __shared__ float As[16][68];
    __shared__ float Bs[16][68];
    const int n0 = blockIdx.x * 64;
    const int m0 = blockIdx.y * 64;
    const bool isP = (m0 >= 1024);
    const float* in   = isP ? ptok : ltok;
    const float* W    = isP ? Wp : Wl;
    const float* bias = isP ? bp : bl;
    const int mb = isP ? (m0 - 1024) : m0;
    float* outp = isP ? g_pproj : g_lproj;
    const int tid = threadIdx.x;
    const int tx = tid & 15, ty = tid >> 4;
    const int lr = tid >> 2, lc = (tid & 3) * 4;
    float acc[4][4] = {};
    for (int kt = 0; kt < 256; kt += 16) {
        float4 a4 = *(const float4*)&in[(mb + lr) * 256 + kt + lc];
        float4 b4 = *(const float4*)&W[(n0 + lr) * 256 + kt + lc];
        As[lc + 0][lr] = a4.x; As[lc + 1][lr] = a4.y; As[lc + 2][lr] = a4.z; As[lc + 3][lr] = a4.w;
        Bs[lc + 0][lr] = b4.x; Bs[lc + 1][lr] = b4.y; Bs[lc + 2][lr] = b4.z; Bs[lc + 3][lr] = b4.w;
        __syncthreads();
#pragma unroll
        for (int e = 0; e < 16; e++) {
            float4 av = *(const float4*)&As[e][ty * 4];
            float4 bv = *(const float4*)&Bs[e][tx * 4];
            acc[0][0] += av.x * bv.x; acc[0][1] += av.x * bv.y; acc[0][2] += av.x * bv.z; acc[0][3] += av.x * bv.w;
            acc[1][0] += av.y * bv.x; acc[1][1] += av.y * bv.y; acc[1][2] += av.y * bv.z; acc[1][3] += av.y * bv.w;
            acc[2][0] += av.z * bv.x; acc[2][1] += av.z * bv.y; acc[2][2] += av.z * bv.z; acc[2][3] += av.z * bv.w;
            acc[3][0] += av.w * bv.x; acc[3][1] += av.w * bv.y; acc[3][2] += av.w * bv.z; acc[3][3] += av.w * bv.w;
        }
        __syncthreads();
    }
#pragma unroll
    for (int ii = 0; ii < 4; ii++)
#pragma unroll
        for (int jj = 0; jj < 4; jj++) {
            int n = n0 + tx * 4 + jj;
            outp[(mb + ty * 4 + ii) * 256 + n] = acc[ii][jj] + bias[n];
        }
}

// -------------------- A1/B1 GEMM (R1, proven) --------------------
__global__ __launch_bounds__(256) void a1b1_kernel(
    const float* __restrict__ W1, const float* __restrict__ b1)
{
    __shared__ float As[16][68];
    __shared__ float Bs[16][68];
    const int n0 = blockIdx.x * 64;
    const int m0 = blockIdx.y * 64;
    const bool isP = (m0 >= 1024);
    const float* in = isP ? g_pproj : g_lproj;
    const int mb = isP ? (m0 - 1024) : m0;
    const int colOff = isP ? 256 : 0;
    float* outp = isP ? g_B1 : g_A1;
    const int tid = threadIdx.x;
    const int tx = tid & 15, ty = tid >> 4;
    const int lr = tid >> 2, lc = (tid & 3) * 4;
    float acc[4][4] = {};
    for (int kt = 0; kt < 256; kt += 16) {
        float4 a4 = *(const float4*)&in[(mb + lr) * 256 + kt + lc];
        float4 b4 = *(const float4*)&W1[(n0 + lr) * 1024 + colOff + kt + lc];
        As[lc + 0][lr] = a4.x; As[lc + 1][lr] = a4.y; As[lc + 2][lr] = a4.z; As[lc + 3][lr] = a4.w;
        Bs[lc + 0][lr] = b4.x; Bs[lc + 1][lr] = b4.y; Bs[lc + 2][lr] = b4.z; Bs[lc + 3][lr] = b4.w;
        __syncthreads();
#pragma unroll
        for (int e = 0; e < 16; e++) {
            float4 av = *(const float4*)&As[e][ty * 4];
            float4 bv = *(const float4*)&Bs[e][tx * 4];
            acc[0][0] += av.x * bv.x; acc[0][1] += av.x * bv.y; acc[0][2] += av.x * bv.z; acc[0][3] += av.x * bv.w;
            acc[1][0] += av.y * bv.x; acc[1][1] += av.y * bv.y; acc[1][2] += av.y * bv.z; acc[1][3] += av.y * bv.w;
            acc[2][0] += av.z * bv.x; acc[2][1] += av.z * bv.y; acc[2][2] += av.z * bv.z; acc[2][3] += av.z * bv.w;
            acc[3][0] += av.w * bv.x; acc[3][1] += av.w * bv.y; acc[3][2] += av.w * bv.z; acc[3][3] += av.w * bv.w;
        }
        __syncthreads();
    }
#pragma unroll
    for (int ii = 0; ii < 4; ii++)
#pragma unroll
        for (int jj = 0; jj < 4; jj++) {
            int n = n0 + tx * 4 + jj;
            float bv = isP ? 0.0f : b1[n];
            outp[(mb + ty * 4 + ii) * 128 + n] = acc[ii][jj] + bv;
        }
}

// -------------------- tensor-core pair kernel (R12) --------------------
#define SM_LH32  0u
#define SM_PH    8448u
#define SM_PH32  16896u
#define SM_X0    25344u
#define SM_X1    62208u
#define SM_W0    99072u
#define SM_W1B   117504u
#define SM_A1    135936u
#define SM_B1    144384u
#define SM_YH(c)  ((c) * 20480u)
#define SM_W2H    81920u           // [128][272B]
#define SM_ZP     116736u          // [4][256] f32
#define SMEM_PAIR 152832

__global__ __launch_bounds__(512, 1) void pair_kernel(
    const float* __restrict__ b2g, const float* __restrict__ W3,
    const float* __restrict__ b3, float* __restrict__ out)
{
    extern __shared__ char smc[];
    float* A1s = (float*)(smc + SM_A1);
    float* B1s = (float*)(smc + SM_B1);
    const uint32_t sbase = smem_u32(smc);

    const int tid  = threadIdx.x;
    const int lane = tid & 31;
    const int wid  = tid >> 5;
    const int mw   = wid & 3;
    const int nw   = wid >> 2;
    const int b  = blockIdx.z;
    const int it = blockIdx.y * 16;
    const int jt = blockIdx.x * 16;

    const uint32_t xOff[2] = {SM_X0, SM_X1};
    const uint32_t wOff[2] = {SM_W0, SM_W1B};

    const uint32_t a_row  = (lane & 7) + ((lane >> 3) & 1) * 8;
    const uint32_t a_colh = ((lane >> 4) & 1) * 16;
    const uint32_t b_row16 = (lane & 7) + ((lane >> 4) & 1) * 8;
    const uint32_t b_colh  = ((lane >> 3) & 1) * 16;

    {
        const float* lsrc = g_lproj + (size_t)(b * 256 + it) * 256;
        const float* psrc = g_pproj + (size_t)(b * 256 + jt) * 256;
        int r = tid >> 5;
        int c = (tid & 31) * 8;
        const float* lr_ = lsrc + r * 256 + c;
        const float* pr_ = psrc + r * 256 + c;
        float4 l0 = *(const float4*)lr_;
        float4 l1 = *(const float4*)(lr_ + 4);
        float4 p0 = *(const float4*)pr_;
        float4 p1 = *(const float4*)(pr_ + 4);
        uint4 lh;
        lh.x = packh(XSCALE * l0.x, XSCALE * l0.y);
        lh.y = packh(XSCALE * l0.z, XSCALE * l0.w);
        lh.z = packh(XSCALE * l1.x, XSCALE * l1.y);
        lh.w = packh(XSCALE * l1.z, XSCALE * l1.w);
        *(uint4*)(smc + SM_LH32 + r * 528 + c * 2) = lh;
        uint4 ph;
        ph.x = packh(p0.x, p0.y);
        ph.y = packh(p0.z, p0.w);
        ph.z = packh(p1.x, p1.y);
        ph.w = packh(p1.z, p1.w);
        *(uint4*)(smc + SM_PH + r * 528 + c * 2) = ph;
        uint4 ph32;
        ph32.x = packh(XSCALE * p0.x, XSCALE * p0.y);
        ph32.y = packh(XSCALE * p0.z, XSCALE * p0.w);
        ph32.z = packh(XSCALE * p1.x, XSCALE * p1.y);
        ph32.w = packh(XSCALE * p1.z, XSCALE * p1.w);
        *(uint4*)(smc + SM_PH32 + r * 528 + c * 2) = ph32;

        const float* a1src = g_A1 + (size_t)(b * 256 + it) * 128;
        const float* b1src = g_B1 + (size_t)(b * 256 + jt) * 128;
        int rc = (tid & 31) * 4;
        *(float4*)&A1s[r * 132 + rc] = *(const float4*)&a1src[r * 128 + rc];
        *(float4*)&B1s[r * 132 + rc] = *(const float4*)&b1src[r * 128 + rc];
    }

    float acc[4][4][4];
#pragma unroll
    for (int mt = 0; mt < 4; mt++)
#pragma unroll
        for (int nt = 0; nt < 4; nt++)
#pragma unroll
            for (int r = 0; r < 4; r++) acc[mt][nt][r] = 0.0f;

    const int bp_ = tid & 255;
    const int bkh = tid >> 8;
    const char* lbase   = smc + SM_LH32 + (bp_ >> 4) * 528;
    const char* pbase   = smc + SM_PH   + (bp_ & 15) * 528;
    const char* p32base = smc + SM_PH32 + (bp_ & 15) * 528;

    __syncthreads();

#define BUILD_CHUNK(cn, sn) do { \
        const bool mul_ = ((cn) < 4); \
        const int kb_ = ((cn) & 3) * 64 + bkh * 32; \
        const uint4* ls_ = (const uint4*)(lbase + kb_ * 2); \
        const uint4* ps_ = (const uint4*)((mul_ ? pbase : p32base) + kb_ * 2); \
        char* dst_ = smc + xOff[sn] + bp_ * 144 + bkh * 64; \
        _Pragma("unroll") \
        for (int q_ = 0; q_ < 4; q_++) { \
            uint4 lv_ = ls_[q_]; \
            uint4 pv_ = ps_[q_]; \
            uint4 ov_; \
            if (mul_) { \
                ov_.x = hmul2u(lv_.x, pv_.x); ov_.y = hmul2u(lv_.y, pv_.y); \
                ov_.z = hmul2u(lv_.z, pv_.z); ov_.w = hmul2u(lv_.w, pv_.w); \
            } else { \
                ov_.x = habsdiff2u(lv_.x, pv_.x); ov_.y = habsdiff2u(lv_.y, pv_.y); \
                ov_.z = habsdiff2u(lv_.z, pv_.z); ov_.w = habsdiff2u(lv_.w, pv_.w); \
            } \
            *(uint4*)(dst_ + q_ * 16) = ov_; \
        } \
        const int wr_ = tid >> 2; \
        const int ws_ = tid & 3; \
        const uint4* wsrc_ = (const uint4*)(g_W1h + wr_ * 512 + (cn) * 64 + ws_ * 16); \
        char* wdst_ = smc + wOff[sn] + wr_ * 144 + ws_ * 32; \
        *(uint4*)(wdst_)      = wsrc_[0]; \
        *(uint4*)(wdst_ + 16) = wsrc_[1]; \
    } while (0)

    BUILD_CHUNK(0, 0);
    __syncthreads();

    for (int c = 0; c < 8; c++) {
        const int s = c & 1;
        if (c + 1 < 8) BUILD_CHUNK(c + 1, (c + 1) & 1);
#pragma unroll
        for (int ks = 0; ks < 4; ks++) {
            uint32_t ah[4][4];
            uint32_t bh[2][4];
#pragma unroll
            for (int mt = 0; mt < 4; mt++) {
                uint32_t rowa = (uint32_t)(mw * 64 + mt * 16) + a_row;
                ldsm_x4(ah[mt], sbase + xOff[s] + rowa * 144 + ks * 32 + a_colh);
            }
#pragma unroll
            for (int ntp = 0; ntp < 2; ntp++) {
                uint32_t rowb = (uint32_t)(nw * 32 + ntp * 16) + b_row16;
                ldsm_x4(bh[ntp], sbase + wOff[s] + rowb * 144 + ks * 32 + b_colh);
            }
#pragma unroll
            for (int ntp = 0; ntp < 2; ntp++)
#pragma unroll
                for (int half = 0; half < 2; half++)
#pragma unroll
                    for (int mt = 0; mt < 4; mt++)
                        mma_f16(acc[mt][ntp * 2 + half], ah[mt],
                                bh[ntp][half * 2], bh[ntp][half * 2 + 1]);
        }
        __syncthreads();
    }
#undef BUILD_CHUNK

#pragma unroll
    for (int mt = 0; mt < 4; mt++) {
#pragma unroll
        for (int rh = 0; rh < 2; rh++) {
            int row = mw * 64 + mt * 16 + (lane >> 2) + rh * 8;
            int il = row >> 4, jl = row & 15;
#pragma unroll
            for (int nt = 0; nt < 4; nt++) {
                int colb = nw * 32 + nt * 8 + (lane & 3) * 2;
                float2 a1v = *(const float2*)&A1s[il * 132 + colb];
                float2 b1v = *(const float2*)&B1s[jl * 132 + colb];
                acc[mt][nt][rh * 2 + 0] = gelu_f(acc[mt][nt][rh * 2 + 0] * XINV + a1v.x + b1v.x);
                acc[mt][nt][rh * 2 + 1] = gelu_f(acc[mt][nt][rh * 2 + 1] * XINV + a1v.y + b1v.y);
            }
        }
    }
    __syncthreads();

#pragma unroll
    for (int mt = 0; mt < 4; mt++) {
#pragma unroll
        for (int nt = 0; nt < 4; nt++) {
#pragma unroll
            for (int rh = 0; rh < 2; rh++) {
                int row = mw * 64 + mt * 16 + (lane >> 2) + rh * 8;
                int cloc = nt * 8 + (lane & 3) * 2;
                uint32_t hp = packh(XSCALE * acc[mt][nt][rh * 2 + 0],
                                    XSCALE * acc[mt][nt][rh * 2 + 1]);
                *(uint32_t*)(smc + SM_YH(nw) + row * 80 + cloc * 2) = hp;
            }
        }
    }
    {
        const int wr = tid >> 2;
        const int ws = tid & 3;
        const uint4* wsrc = (const uint4*)(g_W2h + wr * 128 + ws * 32);
        char* wdst = smc + SM_W2H + wr * 272 + ws * 64;
        *(uint4*)(wdst)      = wsrc[0];
        *(uint4*)(wdst + 16) = wsrc[1];
        *(uint4*)(wdst + 32) = wsrc[2];
        *(uint4*)(wdst + 48) = wsrc[3];
    }
#pragma unroll
    for (int mt = 0; mt < 4; mt++)
#pragma unroll
        for (int nt = 0; nt < 4; nt++)
#pragma unroll
            for (int r = 0; r < 4; r++) acc[mt][nt][r] = 0.0f;
    __syncthreads();

#pragma unroll
    for (int ks = 0; ks < 8; ks++) {
        uint32_t ah[4][4];
        uint32_t bh[2][4];
#pragma unroll
        for (int mt = 0; mt < 4; mt++) {
            uint32_t rowa = (uint32_t)(mw * 64 + mt * 16) + a_row;
            ldsm_x4(ah[mt], sbase + SM_YH(ks >> 1) + rowa * 80 + (ks & 1) * 32 + a_colh);
        }
#pragma unroll
        for (int ntp = 0; ntp < 2; ntp++) {
            uint32_t rowb = (uint32_t)(nw * 32 + ntp * 16) + b_row16;
            ldsm_x4(bh[ntp], sbase + SM_W2H + rowb * 272 + ks * 32 + b_colh);
        }
#pragma unroll
        for (int ntp = 0; ntp < 2; ntp++)
#pragma unroll
            for (int half = 0; half < 2; half++)
#pragma unroll
                for (int mt = 0; mt < 4; mt++)
                    mma_f16(acc[mt][ntp * 2 + half], ah[mt],
                            bh[ntp][half * 2], bh[ntp][half * 2 + 1]);
    }
    __syncthreads();

    {
        float part[4][2];
#pragma unroll
        for (int mt = 0; mt < 4; mt++) { part[mt][0] = 0.0f; part[mt][1] = 0.0f; }
#pragma unroll
        for (int nt = 0; nt < 4; nt++) {
            int colb = nw * 32 + nt * 8 + (lane & 3) * 2;
            float w3a = __ldg(W3 + colb), w3b = __ldg(W3 + colb + 1);
            float b2a = __ldg(b2g + colb), b2b = __ldg(b2g + colb + 1);
#pragma unroll
            for (int mt = 0; mt < 4; mt++) {
                part[mt][0] += w3a * gelu_f(acc[mt][nt][0] * XINV + b2a) + w3b * gelu_f(acc[mt][nt][1] * XINV + b2b);
                part[mt][1] += w3a * gelu_f(acc[mt][nt][2] * XINV + b2a) + w3b * gelu_f(acc[mt][nt][3] * XINV + b2b);
            }
        }
#pragma unroll
        for (int off = 1; off <= 2; off <<= 1) {
#pragma unroll
            for (int mt = 0; mt < 4; mt++) {
                part[mt][0] += __shfl_xor_sync(0xFFFFFFFFu, part[mt][0], off);
                part[mt][1] += __shfl_xor_sync(0xFFFFFFFFu, part[mt][1], off);
            }
        }
        if ((lane & 3) == 0) {
            float* ZP = (float*)(smc + SM_ZP);
#pragma unroll
            for (int mt = 0; mt < 4; mt++) {
                int row0 = mw * 64 + mt * 16 + (lane >> 2);
                ZP[nw * 256 + row0]     = part[mt][0];
                ZP[nw * 256 + row0 + 8] = part[mt][1];
            }
        }
    }
    __syncthreads();
    if (tid < 256) {
        const float* ZP = (const float*)(smc + SM_ZP);
        float v = ZP[tid] + ZP[256 + tid] + ZP[512 + tid] + ZP[768 + tid] + b3[0];
        if (isnan(v)) v = 0.0f;
        else if (isinf(v)) v = (v > 0.0f) ? 20.0f : -20.0f;
        const int gi = it + (tid >> 4);
        const int gj = jt + (tid & 15);
        if (g_lmask[b * 256 + gi] || g_pmask[b * 256 + gj]) v = -20.0f;
        const int idx = 4 + (b * 65536 + gi * 256 + gj);
        out[idx] = v;
        out[idx + 262144] = 1.0f / (1.0f + expf(-v));
    }
}

// -------------------- top-k: R12 byte-radix, 8 elems/thread ILP -------------
__device__ __forceinline__ int wredsum_i(int v) {
#pragma unroll
    for (int o = 16; o; o >>= 1) v += __shfl_xor_sync(0xFFFFFFFFu, v, o);
    return v;
}
__device__ __forceinline__ float wredsum_f(float v) {
#pragma unroll
    for (int o = 16; o; o >>= 1) v += __shfl_xor_sync(0xFFFFFFFFu, v, o);
    return v;
}
__device__ __forceinline__ unsigned fkey(float v) {
    unsigned u = __float_as_uint(v);
    return (u & 0x80000000u) ? ~u : (u | 0x80000000u);
}

__global__ __launch_bounds__(1024) void topk_kernel(float* out) {
    const int b = blockIdx.x;
    const float* data = out + 4 + b * NPAIR_B;
    const int tid = threadIdx.x, lane = tid & 31, wid = tid >> 5;
    __shared__ int histW[32][257];
    __shared__ unsigned s_pref;
    __shared__ int s_above;
    __shared__ float sf[32], sf2[32];
    __shared__ int si[32];

    unsigned prefix = 0u;
    int above = 0;
    for (int pass = 0; pass < 4; pass++) {
        const int bpos = 24 - 8 * pass;
        for (int i = tid; i < 32 * 257; i += 1024) (&histW[0][0])[i] = 0;
        __syncthreads();
        const unsigned maskHi = (pass == 0) ? 0u : (0xFFFFFFFFu << (bpos + 8));
        int* myhist = histW[wid];
#pragma unroll 2
        for (int i = tid * 8; i < NPAIR_B; i += 8192) {
            float4 v4 = *(const float4*)(data + i);
            float4 v4b = *(const float4*)(data + i + 4);
            unsigned kk[8] = {fkey(v4.x), fkey(v4.y), fkey(v4.z), fkey(v4.w),
                              fkey(v4b.x), fkey(v4b.y), fkey(v4b.z), fkey(v4b.w)};
#pragma unroll
            for (int q = 0; q < 8; q++)
                if (((kk[q] ^ prefix) & maskHi) == 0)
                    atomicAdd(&myhist[(kk[q] >> bpos) & 255], 1);
        }
        __syncthreads();
        if (tid < 256) {
            int s = 0;
#pragma unroll
            for (int w = 0; w < 32; w++) s += histW[w][tid];
            histW[0][tid] = s;
        }
        __syncthreads();
        if (tid == 0) {
            int run = 0, chosen = 0, abv = above;
            for (int x = 255; x >= 0; --x) {
                int nr = run + histW[0][x];
                if (above + nr >= TOPK_K) { chosen = x; abv = above + run; break; }
                run = nr;
            }
            s_pref = prefix | ((unsigned)chosen << bpos);
            s_above = abv;
        }
        __syncthreads();
        prefix = s_pref;
        above = s_above;
        __syncthreads();
    }

    unsigned ut = (prefix & 0x80000000u) ? (prefix & 0x7FFFFFFFu) : ~prefix;
    const float vT = __uint_as_float(ut);

    float s1 = 0.0f, s2 = 0.0f;
    int cg = 0;
#pragma unroll 2
    for (int i = tid * 8; i < NPAIR_B; i += 8192) {
        float4 v4 = *(const float4*)(data + i);
        float4 v4b = *(const float4*)(data + i + 4);
        float vv[8] = {v4.x, v4.y, v4.z, v4.w, v4b.x, v4b.y, v4b.z, v4b.w};
#pragma unroll
        for (int q = 0; q < 8; q++) {
            if (fkey(vv[q]) > prefix) {
                float e = __expf(vv[q] - vT);
                s1 += e; s2 += e * vv[q]; cg++;
            }
        }
    }
    s1 = wredsum_f(s1);
    s2 = wredsum_f(s2);
    cg = wredsum_i(cg);
    if (lane == 0) { sf[wid] = s1; sf2[wid] = s2; si[wid] = cg; }
    __syncthreads();
    if (tid == 0) {
        float S1 = 0.0f, S2 = 0.0f;
        int CG = 0;
        for (int w = 0; w < 32; w++) { S1 += sf[w]; S2 += sf2[w]; CG += si[w]; }
        int r = TOPK_K - CG;
        S1 += (float)r;
        S2 += (float)r * vT;
        out[b] = S2 / S1;
    }
}

// ---------------------------------------------------------------------------
extern "C" void kernel_launch(void* const* d_in, const int* in_sizes, int n_in,
                              void* d_out, int out_size)
{
    const float* ltok = (const float*)d_in[0];
    const float* ptok = (const float*)d_in[1];
    const void*  lpad = d_in[2];
    const void*  ppad = d_in[3];
    const float* Wl = (const float*)d_in[4];
    const float* bl = (const float*)d_in[5];
    const float* Wp = (const float*)d_in[6];
    const float* bp = (const float*)d_in[7];
    const float* W1 = (const float*)d_in[8];
    const float* b1 = (const float*)d_in[9];
    const float* W2 = (const float*)d_in[10];
    const float* b2 = (const float*)d_in[11];
    const float* W3 = (const float*)d_in[12];
    const float* b3 = (const float*)d_in[13];
    float* out = (float*)d_out;

    prep_kernel<<<82, 1024>>>(lpad, ppad, W1, W2);
    proj_kernel<<<dim3(4, 32), 256>>>(ltok, ptok, Wl, bl, Wp, bp);
    a1b1_kernel<<<dim3(2, 32), 256>>>(W1, b1);

    cudaFuncSetAttribute(pair_kernel, cudaFuncAttributeMaxDynamicSharedMemorySize, SMEM_PAIR);
    pair_kernel<<<dim3(16, 16, 4), 512, SMEM_PAIR>>>(b2, W3, b3, out);

    topk_kernel<<<4, 1024>>>(out);
}